// round 12
// baseline (speedup 1.0000x reference)
#include <cuda_runtime.h>
#include <cuda_fp16.h>
#include <cstdint>

#define B_ROWS    16384
#define KDIM      192
#define CDIM      256
#define TILE_M    64
#define NTILES    (B_ROWS / TILE_M)    // 256
#define GROUP     9                    // 8 gather blocks + 1 gemm block
#define GRID      (NTILES * GROUP)     // 2304
#define NTHREADS  256
#define WBLOCKS   32                   // W-conv spread over first 32 gather blocks
#define WSLICE    (12288 / WBLOCKS)    // float4 per W-conv block

// ===================== globals =====================
__device__ __half g_X[B_ROWS * KDIM];
__device__ __half g_W[CDIM * KDIM];
__device__ int    g_cnt[NTILES];
__device__ int    g_wcnt;

// ===================== smem layout (gemm role) =====================
#define STRIDE_X  400                    // 192 half = 384B + 16 pad
#define STRIDE_W  208                    // 96 half = 192B + 16 pad
#define OFF_X     0
#define XSZ       (TILE_M * STRIDE_X)    // 25600
#define OFF_W     XSZ
#define WSZ       (256 * STRIDE_W)       // 53248
#define OFF_PAR   (OFF_W + WSZ)          // 78848
#define OFF_PART  (OFF_PAR + 3 * 256 * 4)      // 81920
#define SMEM_SZ   (OFF_PART + TILE_M * 4 * 8)  // 83968 -> 2 blocks/SM

__device__ __forceinline__ uint32_t smem_u32(const void* p) {
    uint32_t a;
    asm("{ .reg .u64 t; cvta.to.shared.u64 t, %1; cvt.u32.u64 %0, t; }"
        : "=r"(a) : "l"(p));
    return a;
}
__device__ __forceinline__ void cp_async16(uint32_t dst, const void* src) {
    asm volatile("cp.async.cg.shared.global [%0], [%1], 16;"
        :: "r"(dst), "l"(src));
}
#define CP_COMMIT()   asm volatile("cp.async.commit_group;" ::: "memory")
#define CP_WAIT_ALL() asm volatile("cp.async.wait_all;" ::: "memory")

__device__ __forceinline__ void ldsm_x4(uint32_t r[4], uint32_t addr) {
    asm volatile("ldmatrix.sync.aligned.m8n8.x4.shared.b16 {%0,%1,%2,%3}, [%4];"
        : "=r"(r[0]), "=r"(r[1]), "=r"(r[2]), "=r"(r[3]) : "r"(addr));
}
__device__ __forceinline__ void mma16816(float* d, const uint32_t* a,
                                         uint32_t b0, uint32_t b1) {
    asm volatile(
        "mma.sync.aligned.m16n8k16.row.col.f32.f16.f16.f32 "
        "{%0,%1,%2,%3}, {%4,%5,%6,%7}, {%8,%9}, {%0,%1,%2,%3};"
        : "+f"(d[0]), "+f"(d[1]), "+f"(d[2]), "+f"(d[3])
        : "r"(a[0]), "r"(a[1]), "r"(a[2]), "r"(a[3]), "r"(b0), "r"(b1));
}

// stage one W K-half (256 rows x 12 uint4)
__device__ __forceinline__ void cp_w_half(uint32_t sb, int half, int tid) {
    #pragma unroll
    for (int it = 0; it < 12; it++) {                // 3072 / 256
        int i = tid + it * NTHREADS;
        int n = i / 12, q = i - n * 12;
        cp_async16(sb + OFF_W + (uint32_t)(n * STRIDE_W + q * 16),
                   g_W + (size_t)n * KDIM + half * 96 + q * 8);
    }
}

__device__ __forceinline__ void load_frags(uint32_t xb, uint32_t wb,
                                           uint32_t kox, uint32_t kow,
                                           uint32_t a0[4], uint32_t a1[4],
                                           uint32_t b[4][4]) {
    ldsm_x4(a0, xb + kox);
    ldsm_x4(a1, xb + 16 * STRIDE_X + kox);
    #pragma unroll
    for (int j = 0; j < 4; j++)
        ldsm_x4(b[j], wb + j * 16 * STRIDE_W + kow);
}

// ============================================================
// Uber kernel: per tile g, blocks 9g..9g+7 gather, block 9g+8 gemms
// ============================================================
__global__ void __launch_bounds__(NTHREADS, 2) uber_kernel(
    const int*   __restrict__ user_input,
    const float* __restrict__ emb,
    const int*   __restrict__ sc_country_idx,
    const float* __restrict__ sc_country_emb,
    const int*   __restrict__ sc_device_idx,
    const float* __restrict__ sc_device_emb,
    const int*   __restrict__ mf_tags_idx,
    const float* __restrict__ mf_tags_emb,
    const int*   __restrict__ mf_history_idx,
    const float* __restrict__ mf_history_emb,
    const float* __restrict__ fc_w,
    const float* __restrict__ fc_b,
    const float* __restrict__ ln_g,
    const float* __restrict__ ln_b,
    float*       __restrict__ out)
{
    const int g   = blockIdx.x / GROUP;
    const int r   = blockIdx.x - g * GROUP;
    const int tid = threadIdx.x;

    if (r < 8) {
        // ================= gather role =================
        // first 32 gather blocks also convert a W slice (fp32 -> fp16)
        if (g < 4) {
            int wblk = g * 8 + r;
            const float4* w4 = (const float4*)fc_w;
            for (int i = tid; i < WSLICE; i += NTHREADS) {
                int i4 = wblk * WSLICE + i;
                float4 v = w4[i4];
                __half2 p0 = __floats2half2_rn(v.x, v.y);
                __half2 p1 = __floats2half2_rn(v.z, v.w);
                uint2 o;
                o.x = *(uint32_t*)&p0;
                o.y = *(uint32_t*)&p1;
                ((uint2*)g_W)[i4] = o;
            }
            __syncthreads();
            if (tid == 0) { __threadfence(); atomicAdd(&g_wcnt, 1); }
        }

        // 8 warps, one row each: rows g*64 + r*8 + w
        int w    = tid >> 5;
        int lane = tid & 31;
        int row  = g * TILE_M + r * 8 + w;
        int u    = user_input[row];
        int base = row * KDIM;

        float2 e = ((const float2*)(emb + (size_t)u * 64))[lane];
        ((__half2*)(g_X + base))[lane] = __floats2half2_rn(e.x, e.y);

        int ci = sc_country_idx[u];
        int di = sc_device_idx[u];
        g_X[base + 64 + lane] = __float2half_rn(sc_country_emb[(size_t)ci * 32 + lane]);
        g_X[base + 96 + lane] = __float2half_rn(sc_device_emb[(size_t)di * 32 + lane]);

        int ti = (lane < 20) ? mf_tags_idx[(size_t)u * 20 + lane] : 0;
        float tacc = 0.f;
        #pragma unroll
        for (int t = 0; t < 20; t++) {
            int id = __shfl_sync(0xffffffffu, ti, t);
            tacc += mf_tags_emb[(size_t)id * 32 + lane];
        }
        g_X[base + 128 + lane] = __float2half_rn(tacc * (1.f / 20.f));

        int hA = mf_history_idx[(size_t)u * 50 + lane];
        int hB = (lane < 18) ? mf_history_idx[(size_t)u * 50 + 32 + lane] : 0;
        float a0 = 0.f, a1 = 0.f;
        #pragma unroll
        for (int t = 0; t < 32; t++) {
            int id = __shfl_sync(0xffffffffu, hA, t);
            a0 += mf_history_emb[(size_t)id * 32 + lane];
        }
        #pragma unroll
        for (int t = 0; t < 18; t++) {
            int id = __shfl_sync(0xffffffffu, hB, t);
            a1 += mf_history_emb[(size_t)id * 32 + lane];
        }
        g_X[base + 160 + lane] = __float2half_rn((a0 + a1) * (1.f / 50.f));

        __syncthreads();
        if (tid == 0) { __threadfence(); atomicAdd(&g_cnt[g], 1); }
        return;
    }

    // ================= gemm role (tile g) =================
    extern __shared__ __align__(16) char smem[];
    const uint32_t sb = smem_u32(smem);
    const int lane = tid & 31;
    const int w    = tid >> 5;
    const int mgrp = w >> 2;      // 0..1 : rows mgrp*32..+31
    const int ngrp = w & 3;       // 0..3 : cols ngrp*64..+63
    const int m_base = g * TILE_M;
    const int h0 = g & 1;
    const int h1 = h0 ^ 1;

    float*  sPar  = (float*)(smem + OFF_PAR);
    float2* sPart = (float2*)(smem + OFF_PART);   // [64][4] (sum, ss)

    // wait for W conversion, then stage W(h0)
    if (tid == 0) { while (atomicAdd(&g_wcnt, 0) < WBLOCKS) {} __threadfence(); }
    __syncthreads();
    cp_w_half(sb, h0, tid);
    CP_COMMIT();

    sPar[tid]       = fc_b[tid];
    sPar[256 + tid] = ln_g[tid];
    sPar[512 + tid] = ln_b[tid];

    // wait for this tile's gather blocks, then stage X (full K)
    if (tid == 0) { while (atomicAdd(&g_cnt[g], 0) < 8) {} __threadfence(); }
    __syncthreads();
    #pragma unroll
    for (int it = 0; it < 6; it++) {                 // 1536 / 256
        int i = tid + it * NTHREADS;
        int rr = i / 24, q = i - rr * 24;
        cp_async16(sb + OFF_X + (uint32_t)(rr * STRIDE_X + q * 16),
                   g_X + (size_t)(m_base + rr) * KDIM + q * 8);
    }
    CP_COMMIT();
    CP_WAIT_ALL();
    __syncthreads();

    float acc[2][8][4];
    #pragma unroll
    for (int i = 0; i < 2; i++)
        #pragma unroll
        for (int j = 0; j < 8; j++)
            #pragma unroll
            for (int k = 0; k < 4; k++) acc[i][j][k] = 0.f;

    const int rk = lane & 15;
    const uint32_t kbyte = (uint32_t)((lane >> 4) << 4);
    const uint32_t xb = sb + OFF_X + (uint32_t)((mgrp * 32 + rk) * STRIDE_X) + kbyte;
    const uint32_t wb = sb + OFF_W + (uint32_t)((ngrp * 64 + rk) * STRIDE_W) + kbyte;

    #pragma unroll
    for (int ph = 0; ph < 2; ph++) {
        const int half = (ph == 0) ? h0 : h1;
        const uint32_t xbase = (uint32_t)(half * 6) * 32;

        uint32_t A0[2][4], A1[2][4], Bf[2][4][4];
        load_frags(xb, wb, xbase, 0, A0[0], A1[0], Bf[0]);
        #pragma unroll
        for (int s = 0; s < 6; s++) {
            int cur = s & 1, nxt = cur ^ 1;
            if (s < 5)
                load_frags(xb, wb, xbase + (uint32_t)(s + 1) * 32,
                           (uint32_t)(s + 1) * 32, A0[nxt], A1[nxt], Bf[nxt]);
            #pragma unroll
            for (int j = 0; j < 4; j++) {
                mma16816(acc[0][2*j],     A0[cur], Bf[cur][j][0], Bf[cur][j][2]);
                mma16816(acc[0][2*j + 1], A0[cur], Bf[cur][j][1], Bf[cur][j][3]);
                mma16816(acc[1][2*j],     A1[cur], Bf[cur][j][0], Bf[cur][j][2]);
                mma16816(acc[1][2*j + 1], A1[cur], Bf[cur][j][1], Bf[cur][j][3]);
            }
        }

        if (ph == 0) {
            __syncthreads();                 // all warps done reading W(h0)
            cp_w_half(sb, h1, tid);
            CP_COMMIT();
            CP_WAIT_ALL();
            __syncthreads();
        }
    }

    // ---- bias + relu in registers; per-row partial sums ----
    const int c0 = ngrp * 64 + (lane & 3) * 2;
    float ysum[4] = {0.f, 0.f, 0.f, 0.f};
    float yss[4]  = {0.f, 0.f, 0.f, 0.f};
    #pragma unroll
    for (int mf = 0; mf < 2; mf++)
        #pragma unroll
        for (int nf = 0; nf < 8; nf++) {
            int c = c0 + nf * 8;
            float b0 = sPar[c], b1 = sPar[c + 1];
            float v0 = fmaxf(acc[mf][nf][0] + b0, 0.f);
            float v1 = fmaxf(acc[mf][nf][1] + b1, 0.f);
            float v2 = fmaxf(acc[mf][nf][2] + b0, 0.f);
            float v3 = fmaxf(acc[mf][nf][3] + b1, 0.f);
            acc[mf][nf][0] = v0; acc[mf][nf][1] = v1;
            acc[mf][nf][2] = v2; acc[mf][nf][3] = v3;
            ysum[mf*2]     += v0 + v1;
            yss[mf*2]      += v0*v0 + v1*v1;
            ysum[mf*2 + 1] += v2 + v3;
            yss[mf*2 + 1]  += v2*v2 + v3*v3;
        }
    #pragma unroll
    for (int i = 0; i < 4; i++) {
        ysum[i] += __shfl_xor_sync(0xffffffffu, ysum[i], 1);
        ysum[i] += __shfl_xor_sync(0xffffffffu, ysum[i], 2);
        yss[i]  += __shfl_xor_sync(0xffffffffu, yss[i],  1);
        yss[i]  += __shfl_xor_sync(0xffffffffu, yss[i],  2);
    }
    if ((lane & 3) == 0) {
        int r0 = mgrp * 32 + (lane >> 2);
        #pragma unroll
        for (int i = 0; i < 4; i++) {
            int rr = r0 + (i >> 1) * 16 + (i & 1) * 8;
            sPart[rr * 4 + ngrp] = make_float2(ysum[i], yss[i]);
        }
    }
    __syncthreads();

    // ---- finalize LN per row, write out from fragments ----
    #pragma unroll
    for (int i = 0; i < 4; i++) {
        int rr = mgrp * 32 + (lane >> 2) + (i >> 1) * 16 + (i & 1) * 8;
        float4 pa = *(const float4*)&sPart[rr * 4];
        float4 pb = *(const float4*)&sPart[rr * 4 + 2];
        float sum = pa.x + pa.z + pb.x + pb.z;
        float ss  = pa.y + pa.w + pb.y + pb.w;
        float mean = sum * (1.f / 256.f);
        float var  = ss * (1.f / 256.f) - mean * mean;
        float rstd = rsqrtf(var + 1e-5f);
        float* orow = out + (size_t)(m_base + rr) * CDIM;
        int mf = i >> 1, kp = (i & 1) * 2;
        #pragma unroll
        for (int nf = 0; nf < 8; nf++) {
            int c = c0 + nf * 8;
            float2 o2;
            o2.x = (acc[mf][nf][kp]     - mean) * rstd * sPar[256 + c]     + sPar[512 + c];
            o2.y = (acc[mf][nf][kp + 1] - mean) * rstd * sPar[256 + c + 1] + sPar[512 + c + 1];
            *(float2*)&orow[c] = o2;
        }
    }
}

// ============================================================
extern "C" void kernel_launch(void* const* d_in, const int* in_sizes, int n_in,
                              void* d_out, int out_size) {
    (void)in_sizes; (void)n_in; (void)out_size;
    const int*   user_input      = (const int*)  d_in[0];
    const float* emb             = (const float*)d_in[1];
    const int*   sc_country_idx  = (const int*)  d_in[2];
    const float* sc_country_emb  = (const float*)d_in[3];
    const int*   sc_device_idx   = (const int*)  d_in[4];
    const float* sc_device_emb   = (const float*)d_in[5];
    const int*   mf_tags_idx     = (const int*)  d_in[6];
    const float* mf_tags_emb     = (const float*)d_in[7];
    const int*   mf_history_idx  = (const int*)  d_in[8];
    const float* mf_history_emb  = (const float*)d_in[9];
    const float* fc_w            = (const float*)d_in[10];
    const float* fc_b            = (const float*)d_in[11];
    const float* ln_g            = (const float*)d_in[12];
    const float* ln_b            = (const float*)d_in[13];
    float* out = (float*)d_out;

    // reset flags (graph-capturable async memsets)
    void* cnt_addr = nullptr;
    void* wcnt_addr = nullptr;
    cudaGetSymbolAddress(&cnt_addr, g_cnt);
    cudaGetSymbolAddress(&wcnt_addr, g_wcnt);
    cudaMemsetAsync(cnt_addr, 0, NTILES * sizeof(int));
    cudaMemsetAsync(wcnt_addr, 0, sizeof(int));

    cudaFuncSetAttribute(uber_kernel,
                         cudaFuncAttributeMaxDynamicSharedMemorySize, SMEM_SZ);
    uber_kernel<<<GRID, NTHREADS, SMEM_SZ>>>(
        user_input, emb,
        sc_country_idx, sc_country_emb,
        sc_device_idx,  sc_device_emb,
        mf_tags_idx,    mf_tags_emb,
        mf_history_idx, mf_history_emb,
        fc_w, fc_b, ln_g, ln_b, out);
}

// round 13
// speedup vs baseline: 1.4298x; 1.4298x over previous
#include <cuda_runtime.h>
#include <cuda_fp16.h>
#include <cstdint>

#define B_ROWS    16384
#define KDIM      192
#define CDIM      256
#define NTILES    (B_ROWS / 128)       // 128 gemm tiles

// ===================== scratch =====================
__device__ __half g_X[B_ROWS * KDIM];
__device__ __half g_W[CDIM * KDIM];
__device__ int    g_cnt[NTILES];
__device__ int    g_wcnt;

// ============================================================
// Kernel A: W-conv blocks FIRST, then gather (one warp per row)
//   every block triggers programmatic launch completion at start
// ============================================================
#define WCONV_BLOCKS  12
#define GATHER_BLOCKS (B_ROWS / 8)     // 2048

__global__ void __launch_bounds__(256) gather_kernel(
    const int*   __restrict__ user_input,
    const float* __restrict__ emb,
    const int*   __restrict__ sc_country_idx,
    const float* __restrict__ sc_country_emb,
    const int*   __restrict__ sc_device_idx,
    const float* __restrict__ sc_device_emb,
    const int*   __restrict__ mf_tags_idx,
    const float* __restrict__ mf_tags_emb,
    const int*   __restrict__ mf_history_idx,
    const float* __restrict__ mf_history_emb,
    const float* __restrict__ fc_w)
{
    cudaTriggerProgrammaticLaunchCompletion();

    if (blockIdx.x < WCONV_BLOCKS) {
        // ---- W conversion: fp32 -> fp16 (1024 float4 per block) ----
        int gid = blockIdx.x * 1024 + threadIdx.x;
        const float4* w4 = (const float4*)fc_w;
        #pragma unroll
        for (int j = 0; j < 4; j++) {
            int i4 = gid + j * 256;
            float4 v = w4[i4];
            __half2 p0 = __floats2half2_rn(v.x, v.y);
            __half2 p1 = __floats2half2_rn(v.z, v.w);
            uint2 o;
            o.x = *(uint32_t*)&p0;
            o.y = *(uint32_t*)&p1;
            ((uint2*)g_W)[i4] = o;
        }
        __syncthreads();
        if (threadIdx.x == 0) { __threadfence(); atomicAdd(&g_wcnt, 1); }
        return;
    }

    int blk  = blockIdx.x - WCONV_BLOCKS;       // 0..2047
    int w    = threadIdx.x >> 5;
    int lane = threadIdx.x & 31;
    int row  = blk * 8 + w;

    int u = user_input[row];
    int base = row * KDIM;

    // main embedding: 64 fp32 -> half2
    float2 e = ((const float2*)(emb + (size_t)u * 64))[lane];
    ((__half2*)(g_X + base))[lane] = __floats2half2_rn(e.x, e.y);

    // scalar side features
    int ci = sc_country_idx[u];
    int di = sc_device_idx[u];
    g_X[base + 64 + lane] = __float2half_rn(sc_country_emb[(size_t)ci * 32 + lane]);
    g_X[base + 96 + lane] = __float2half_rn(sc_device_emb[(size_t)di * 32 + lane]);

    // tags: mean over 20
    int ti = (lane < 20) ? mf_tags_idx[(size_t)u * 20 + lane] : 0;
    float tacc = 0.f;
    #pragma unroll
    for (int t = 0; t < 20; t++) {
        int id = __shfl_sync(0xffffffffu, ti, t);
        tacc += mf_tags_emb[(size_t)id * 32 + lane];
    }
    g_X[base + 128 + lane] = __float2half_rn(tacc * (1.f / 20.f));

    // history: mean over 50
    int hA = mf_history_idx[(size_t)u * 50 + lane];
    int hB = (lane < 18) ? mf_history_idx[(size_t)u * 50 + 32 + lane] : 0;
    float a0 = 0.f, a1 = 0.f;
    #pragma unroll
    for (int t = 0; t < 32; t++) {
        int id = __shfl_sync(0xffffffffu, hA, t);
        a0 += mf_history_emb[(size_t)id * 32 + lane];
    }
    #pragma unroll
    for (int t = 0; t < 18; t++) {
        int id = __shfl_sync(0xffffffffu, hB, t);
        a1 += mf_history_emb[(size_t)id * 32 + lane];
    }
    g_X[base + 160 + lane] = __float2half_rn((a0 + a1) * (1.f / 50.f));

    __syncthreads();
    if (threadIdx.x == 0) { __threadfence(); atomicAdd(&g_cnt[blk >> 4], 1); }
}

// ============================================================
// Kernel B: fp16 HMMA GEMM + bias/relu/LN (fragment-level LN)
//   512 thr = 16 warps (4m x 4n), warp 32x64, CTA 128x256
//   single-buffered frags, reg-capped for PDL co-residence
// ============================================================
#define GEMM_THREADS 512
#define STRIDE_B  400                    // 192 half = 384B + 16 pad
#define XSZ       (128 * STRIDE_B)       // 51200
#define OFF_W     XSZ
#define WSZ       (256 * STRIDE_B)       // 102400
#define OFF_PAR   (OFF_W + WSZ)          // 153600
#define OFF_PART  (OFF_PAR + 3 * 256 * 4)           // 156672
#define SMEM_SZ   (OFF_PART + 128 * 4 * 8)          // 160768

__device__ __forceinline__ uint32_t smem_u32(const void* p) {
    uint32_t a;
    asm("{ .reg .u64 t; cvta.to.shared.u64 t, %1; cvt.u32.u64 %0, t; }"
        : "=r"(a) : "l"(p));
    return a;
}
__device__ __forceinline__ void cp_async16(uint32_t dst, const void* src) {
    asm volatile("cp.async.cg.shared.global [%0], [%1], 16;"
        :: "r"(dst), "l"(src));
}
#define CP_COMMIT()   asm volatile("cp.async.commit_group;" ::: "memory")
#define CP_WAIT_ALL() asm volatile("cp.async.wait_all;" ::: "memory")

__device__ __forceinline__ void ldsm_x4(uint32_t r[4], uint32_t addr) {
    asm volatile("ldmatrix.sync.aligned.m8n8.x4.shared.b16 {%0,%1,%2,%3}, [%4];"
        : "=r"(r[0]), "=r"(r[1]), "=r"(r[2]), "=r"(r[3]) : "r"(addr));
}
__device__ __forceinline__ void mma16816(float* d, const uint32_t* a,
                                         uint32_t b0, uint32_t b1) {
    asm volatile(
        "mma.sync.aligned.m16n8k16.row.col.f32.f16.f16.f32 "
        "{%0,%1,%2,%3}, {%4,%5,%6,%7}, {%8,%9}, {%0,%1,%2,%3};"
        : "+f"(d[0]), "+f"(d[1]), "+f"(d[2]), "+f"(d[3])
        : "r"(a[0]), "r"(a[1]), "r"(a[2]), "r"(a[3]), "r"(b0), "r"(b1));
}

__global__ void __launch_bounds__(576, 1) gemm_ln_mma_kernel(
    const float* __restrict__ fc_b,
    const float* __restrict__ ln_g,
    const float* __restrict__ ln_b,
    float*       __restrict__ out)    // [B_ROWS][256]
{
    extern __shared__ __align__(16) char smem[];
    const uint32_t sb = smem_u32(smem);
    const int tid  = threadIdx.x;
    const int lane = tid & 31;
    const int w    = tid >> 5;
    const int mgrp = w >> 2;      // rows mgrp*32..+31
    const int ngrp = w & 3;       // cols ngrp*64..+63
    const int m_base = blockIdx.x * 128;

    float*  sPar  = (float*)(smem + OFF_PAR);
    float2* sPart = (float2*)(smem + OFF_PART);   // [128][4] (sum, ss)

    // ---- wait for W conversion, stage W ----
    if (tid == 0) { while (atomicAdd(&g_wcnt, 0) < WCONV_BLOCKS) {} __threadfence_block(); }
    __syncthreads();
    #pragma unroll
    for (int it = 0; it < 12; it++) {
        int i = tid + it * GEMM_THREADS;
        int n = i / 24, q = i - n * 24;
        cp_async16(sb + OFF_W + (uint32_t)(n * STRIDE_B + q * 16),
                   g_W + (size_t)n * KDIM + q * 8);
    }
    CP_COMMIT();

    if (tid < 256) {
        sPar[tid]       = fc_b[tid];
        sPar[256 + tid] = ln_g[tid];
        sPar[512 + tid] = ln_b[tid];
    }

    // ---- wait for this tile's gather blocks, stage X ----
    if (tid == 0) { while (atomicAdd(&g_cnt[blockIdx.x], 0) < 16) {} __threadfence_block(); }
    __syncthreads();
    #pragma unroll
    for (int it = 0; it < 6; it++) {
        int i = tid + it * GEMM_THREADS;
        int r = i / 24, q = i - r * 24;
        cp_async16(sb + (uint32_t)(r * STRIDE_B + q * 16),
                   g_X + (size_t)(m_base + r) * KDIM + q * 8);
    }
    CP_COMMIT();
    CP_WAIT_ALL();
    __syncthreads();

    float acc[2][8][4];
    #pragma unroll
    for (int i = 0; i < 2; i++)
        #pragma unroll
        for (int j = 0; j < 8; j++)
            #pragma unroll
            for (int k = 0; k < 4; k++) acc[i][j][k] = 0.f;

    const int rk = lane & 15;
    const uint32_t kbyte = (uint32_t)((lane >> 4) << 4);
    const uint32_t xb = sb + (uint32_t)((mgrp * 32 + rk) * STRIDE_B) + kbyte;
    const uint32_t wb = sb + OFF_W + (uint32_t)((ngrp * 64 + rk) * STRIDE_B) + kbyte;

    // ---- 12 k16-steps, single-buffered fragments (tensor-bound) ----
    #pragma unroll
    for (int s = 0; s < 12; s++) {
        uint32_t ko = (uint32_t)s * 32;
        uint32_t A0[4], A1[4], Bf[4][4];
        ldsm_x4(A0, xb + ko);
        ldsm_x4(A1, xb + 16 * STRIDE_B + ko);
        #pragma unroll
        for (int j = 0; j < 4; j++)
            ldsm_x4(Bf[j], wb + j * 16 * STRIDE_B + ko);
        #pragma unroll
        for (int j = 0; j < 4; j++) {
            mma16816(acc[0][2*j],     A0, Bf[j][0], Bf[j][2]);
            mma16816(acc[0][2*j + 1], A0, Bf[j][1], Bf[j][3]);
            mma16816(acc[1][2*j],     A1, Bf[j][0], Bf[j][2]);
            mma16816(acc[1][2*j + 1], A1, Bf[j][1], Bf[j][3]);
        }
    }

    // ---- bias + relu in registers; per-row partial sums ----
    const int c0 = ngrp * 64 + (lane & 3) * 2;
    float ysum[4] = {0.f, 0.f, 0.f, 0.f};
    float yss[4]  = {0.f, 0.f, 0.f, 0.f};
    #pragma unroll
    for (int mf = 0; mf < 2; mf++)
        #pragma unroll
        for (int nf = 0; nf < 8; nf++) {
            int c = c0 + nf * 8;
            float b0 = sPar[c], b1 = sPar[c + 1];
            float v0 = fmaxf(acc[mf][nf][0] + b0, 0.f);
            float v1 = fmaxf(acc[mf][nf][1] + b1, 0.f);
            float v2 = fmaxf(acc[mf][nf][2] + b0, 0.f);
            float v3 = fmaxf(acc[mf][nf][3] + b1, 0.f);
            acc[mf][nf][0] = v0; acc[mf][nf][1] = v1;
            acc[mf][nf][2] = v2; acc[mf][nf][3] = v3;
            ysum[mf*2]     += v0 + v1;
            yss[mf*2]      += v0*v0 + v1*v1;
            ysum[mf*2 + 1] += v2 + v3;
            yss[mf*2 + 1]  += v2*v2 + v3*v3;
        }
    #pragma unroll
    for (int i = 0; i < 4; i++) {
        ysum[i] += __shfl_xor_sync(0xffffffffu, ysum[i], 1);
        ysum[i] += __shfl_xor_sync(0xffffffffu, ysum[i], 2);
        yss[i]  += __shfl_xor_sync(0xffffffffu, yss[i],  1);
        yss[i]  += __shfl_xor_sync(0xffffffffu, yss[i],  2);
    }
    if ((lane & 3) == 0) {
        int r0 = mgrp * 32 + (lane >> 2);
        #pragma unroll
        for (int i = 0; i < 4; i++) {
            int r = r0 + (i >> 1) * 16 + (i & 1) * 8;
            sPart[r * 4 + ngrp] = make_float2(ysum[i], yss[i]);
        }
    }
    __syncthreads();

    // ---- finalize LN per row, write out from fragments ----
    #pragma unroll
    for (int i = 0; i < 4; i++) {
        int r = mgrp * 32 + (lane >> 2) + (i >> 1) * 16 + (i & 1) * 8;
        float4 pa = *(const float4*)&sPart[r * 4];
        float4 pb = *(const float4*)&sPart[r * 4 + 2];
        float sum = pa.x + pa.z + pb.x + pb.z;
        float ss  = pa.y + pa.w + pb.y + pb.w;
        float mean = sum * (1.f / 256.f);
        float var  = ss * (1.f / 256.f) - mean * mean;
        float rstd = rsqrtf(var + 1e-5f);
        float* orow = out + (size_t)(m_base + r) * CDIM;
        int mf = i >> 1, kp = (i & 1) * 2;
        #pragma unroll
        for (int nf = 0; nf < 8; nf++) {
            int c = c0 + nf * 8;
            float2 o2;
            o2.x = (acc[mf][nf][kp]     - mean) * rstd * sPar[256 + c]     + sPar[512 + c];
            o2.y = (acc[mf][nf][kp + 1] - mean) * rstd * sPar[256 + c + 1] + sPar[512 + c + 1];
            *(float2*)&orow[c] = o2;
        }
    }
}

// ============================================================
extern "C" void kernel_launch(void* const* d_in, const int* in_sizes, int n_in,
                              void* d_out, int out_size) {
    (void)in_sizes; (void)n_in; (void)out_size;
    const int*   user_input      = (const int*)  d_in[0];
    const float* emb             = (const float*)d_in[1];
    const int*   sc_country_idx  = (const int*)  d_in[2];
    const float* sc_country_emb  = (const float*)d_in[3];
    const int*   sc_device_idx   = (const int*)  d_in[4];
    const float* sc_device_emb   = (const float*)d_in[5];
    const int*   mf_tags_idx     = (const int*)  d_in[6];
    const float* mf_tags_emb     = (const float*)d_in[7];
    const int*   mf_history_idx  = (const int*)  d_in[8];
    const float* mf_history_emb  = (const float*)d_in[9];
    const float* fc_w            = (const float*)d_in[10];
    const float* fc_b            = (const float*)d_in[11];
    const float* ln_g            = (const float*)d_in[12];
    const float* ln_b            = (const float*)d_in[13];
    float* out = (float*)d_out;

    // reset flags (graph-capturable async memsets)
    void* cnt_addr = nullptr;
    void* wcnt_addr = nullptr;
    cudaGetSymbolAddress(&cnt_addr, g_cnt);
    cudaGetSymbolAddress(&wcnt_addr, g_wcnt);
    cudaMemsetAsync(cnt_addr, 0, NTILES * sizeof(int));
    cudaMemsetAsync(wcnt_addr, 0, sizeof(int));

    gather_kernel<<<GATHER_BLOCKS + WCONV_BLOCKS, 256>>>(
        user_input, emb,
        sc_country_idx, sc_country_emb,
        sc_device_idx,  sc_device_emb,
        mf_tags_idx,    mf_tags_emb,
        mf_history_idx, mf_history_emb,
        fc_w);

    cudaFuncSetAttribute(gemm_ln_mma_kernel,
                         cudaFuncAttributeMaxDynamicSharedMemorySize, SMEM_SZ);

    // PDL: gemm launches while gather's tail waves still run
    cudaLaunchConfig_t cfg = {};
    cfg.gridDim  = dim3(NTILES, 1, 1);
    cfg.blockDim = dim3(GEMM_THREADS, 1, 1);
    cfg.dynamicSmemBytes = SMEM_SZ;
    cfg.stream = 0;
    cudaLaunchAttribute attr[1];
    attr[0].id = cudaLaunchAttributeProgrammaticStreamSerialization;
    attr[0].val.programmaticStreamSerializationAllowed = 1;
    cfg.attrs = attr;
    cfg.numAttrs = 1;
    cudaLaunchKernelEx(&cfg, gemm_ln_mma_kernel, fc_b, ln_g, ln_b, out);
}

// round 14
// speedup vs baseline: 1.6128x; 1.1280x over previous
#include <cuda_runtime.h>
#include <cuda_fp16.h>
#include <cstdint>

#define B_ROWS    16384
#define KDIM      192
#define CDIM      256

// ===================== scratch (fp16 X and W) =====================
__device__ __half g_X[B_ROWS * KDIM];
__device__ __half g_W[CDIM * KDIM];

// ============================================================
// Kernel A: W-conv blocks FIRST, then gather (one warp per row)
// ============================================================
#define WCONV_BLOCKS  12
#define GATHER_BLOCKS (B_ROWS / 8)

__global__ void __launch_bounds__(256) gather_kernel(
    const int*   __restrict__ user_input,
    const float* __restrict__ emb,
    const int*   __restrict__ sc_country_idx,
    const float* __restrict__ sc_country_emb,
    const int*   __restrict__ sc_device_idx,
    const float* __restrict__ sc_device_emb,
    const int*   __restrict__ mf_tags_idx,
    const float* __restrict__ mf_tags_emb,
    const int*   __restrict__ mf_history_idx,
    const float* __restrict__ mf_history_emb,
    const float* __restrict__ fc_w)
{
    if (blockIdx.x < WCONV_BLOCKS) {
        // ---- W conversion: fp32 -> fp16 ----
        int gid = blockIdx.x * 256 + threadIdx.x;   // 0..3071
        const float4* w4 = (const float4*)fc_w;
        #pragma unroll
        for (int j = 0; j < 4; j++) {
            int i4 = gid + j * 3072;                // 12288 float4 total
            float4 v = w4[i4];
            __half2 p0 = __floats2half2_rn(v.x, v.y);
            __half2 p1 = __floats2half2_rn(v.z, v.w);
            uint2 o;
            o.x = *(uint32_t*)&p0;
            o.y = *(uint32_t*)&p1;
            ((uint2*)g_W)[i4] = o;
        }
        return;
    }

    int row  = ((blockIdx.x - WCONV_BLOCKS) * blockDim.x + threadIdx.x) >> 5;
    int lane = threadIdx.x & 31;

    int u = user_input[row];
    int base = row * KDIM;

    // main embedding: 64 fp32 -> half2
    float2 e = ((const float2*)(emb + (size_t)u * 64))[lane];
    ((__half2*)(g_X + base))[lane] = __floats2half2_rn(e.x, e.y);

    // scalar side features
    int ci = sc_country_idx[u];
    int di = sc_device_idx[u];
    g_X[base + 64 + lane] = __float2half_rn(sc_country_emb[(size_t)ci * 32 + lane]);
    g_X[base + 96 + lane] = __float2half_rn(sc_device_emb[(size_t)di * 32 + lane]);

    // tags: mean over 20
    int ti = (lane < 20) ? mf_tags_idx[(size_t)u * 20 + lane] : 0;
    float tacc = 0.f;
    #pragma unroll
    for (int t = 0; t < 20; t++) {
        int id = __shfl_sync(0xffffffffu, ti, t);
        tacc += mf_tags_emb[(size_t)id * 32 + lane];
    }
    g_X[base + 128 + lane] = __float2half_rn(tacc * (1.f / 20.f));

    // history: mean over 50
    int hA = mf_history_idx[(size_t)u * 50 + lane];
    int hB = (lane < 18) ? mf_history_idx[(size_t)u * 50 + 32 + lane] : 0;
    float a0 = 0.f, a1 = 0.f;
    #pragma unroll
    for (int t = 0; t < 32; t++) {
        int id = __shfl_sync(0xffffffffu, hA, t);
        a0 += mf_history_emb[(size_t)id * 32 + lane];
    }
    #pragma unroll
    for (int t = 0; t < 18; t++) {
        int id = __shfl_sync(0xffffffffu, hB, t);
        a1 += mf_history_emb[(size_t)id * 32 + lane];
    }
    g_X[base + 160 + lane] = __float2half_rn((a0 + a1) * (1.f / 50.f));
}

// ============================================================
// Kernel B: fp16 HMMA GEMM + bias/relu/LN (fragment-level LN)
//   512 thr = 16 warps (4 m x 4 n), warp tile 32x64, CTA 128x256
//   full K=192 staged once; 12 k-steps, double-buffered frags
// ============================================================
#define GEMM_THREADS 512
#define STRIDE_B  400                    // 192 half = 384B + 16 pad
#define XSZ       (128 * STRIDE_B)       // 51200
#define OFF_W     XSZ
#define WSZ       (256 * STRIDE_B)       // 102400
#define OFF_PAR   (OFF_W + WSZ)          // 153600
#define OFF_PART  (OFF_PAR + 3 * 256 * 4)           // 156672
#define SMEM_SZ   (OFF_PART + 128 * 4 * 8)          // 160768

__device__ __forceinline__ uint32_t smem_u32(const void* p) {
    uint32_t a;
    asm("{ .reg .u64 t; cvta.to.shared.u64 t, %1; cvt.u32.u64 %0, t; }"
        : "=r"(a) : "l"(p));
    return a;
}
__device__ __forceinline__ void cp_async16(uint32_t dst, const void* src) {
    asm volatile("cp.async.cg.shared.global [%0], [%1], 16;"
        :: "r"(dst), "l"(src));
}
#define CP_COMMIT()   asm volatile("cp.async.commit_group;" ::: "memory")
#define CP_WAIT_ALL() asm volatile("cp.async.wait_all;" ::: "memory")

__device__ __forceinline__ void ldsm_x4(uint32_t r[4], uint32_t addr) {
    asm volatile("ldmatrix.sync.aligned.m8n8.x4.shared.b16 {%0,%1,%2,%3}, [%4];"
        : "=r"(r[0]), "=r"(r[1]), "=r"(r[2]), "=r"(r[3]) : "r"(addr));
}
__device__ __forceinline__ void mma16816(float* d, const uint32_t* a,
                                         uint32_t b0, uint32_t b1) {
    asm volatile(
        "mma.sync.aligned.m16n8k16.row.col.f32.f16.f16.f32 "
        "{%0,%1,%2,%3}, {%4,%5,%6,%7}, {%8,%9}, {%0,%1,%2,%3};"
        : "+f"(d[0]), "+f"(d[1]), "+f"(d[2]), "+f"(d[3])
        : "r"(a[0]), "r"(a[1]), "r"(a[2]), "r"(a[3]), "r"(b0), "r"(b1));
}

__device__ __forceinline__ void load_frags(uint32_t xb, uint32_t wb, uint32_t ko,
                                           uint32_t a0[4], uint32_t a1[4],
                                           uint32_t b[4][4]) {
    ldsm_x4(a0, xb + ko);
    ldsm_x4(a1, xb + 16 * STRIDE_B + ko);
    #pragma unroll
    for (int j = 0; j < 4; j++)
        ldsm_x4(b[j], wb + j * 16 * STRIDE_B + ko);
}

__global__ void __launch_bounds__(GEMM_THREADS, 1) gemm_ln_mma_kernel(
    const float* __restrict__ fc_b,
    const float* __restrict__ ln_g,
    const float* __restrict__ ln_b,
    float*       __restrict__ out)    // [B_ROWS][256]
{
    extern __shared__ __align__(16) char smem[];
    const uint32_t sb = smem_u32(smem);
    const int tid  = threadIdx.x;
    const int lane = tid & 31;
    const int w    = tid >> 5;
    const int mgrp = w >> 2;      // rows mgrp*32..+31
    const int ngrp = w & 3;       // cols ngrp*64..+63
    const int m_base = blockIdx.x * 128;

    float*  sPar  = (float*)(smem + OFF_PAR);
    float2* sPart = (float2*)(smem + OFF_PART);   // [128][4] (sum, ss)

    // ---- stage X (128 x 24 uint4) + W (256 x 24 uint4) ----
    #pragma unroll
    for (int it = 0; it < 6; it++) {                 // 3072 / 512
        int i = tid + it * GEMM_THREADS;
        int r = i / 24, q = i - r * 24;
        cp_async16(sb + (uint32_t)(r * STRIDE_B + q * 16),
                   g_X + (size_t)(m_base + r) * KDIM + q * 8);
    }
    #pragma unroll
    for (int it = 0; it < 12; it++) {                // 6144 / 512
        int i = tid + it * GEMM_THREADS;
        int n = i / 24, q = i - n * 24;
        cp_async16(sb + OFF_W + (uint32_t)(n * STRIDE_B + q * 16),
                   g_W + (size_t)n * KDIM + q * 8);
    }
    CP_COMMIT();

    if (tid < 256) {
        sPar[tid]       = fc_b[tid];
        sPar[256 + tid] = ln_g[tid];
        sPar[512 + tid] = ln_b[tid];
    }

    CP_WAIT_ALL();
    __syncthreads();

    float acc[2][8][4];
    #pragma unroll
    for (int i = 0; i < 2; i++)
        #pragma unroll
        for (int j = 0; j < 8; j++)
            #pragma unroll
            for (int k = 0; k < 4; k++) acc[i][j][k] = 0.f;

    const int rk = lane & 15;
    const uint32_t kbyte = (uint32_t)((lane >> 4) << 4);
    const uint32_t xb = sb + (uint32_t)((mgrp * 32 + rk) * STRIDE_B) + kbyte;
    const uint32_t wb = sb + OFF_W + (uint32_t)((ngrp * 64 + rk) * STRIDE_B) + kbyte;

    // ---- 12 k16-steps, double-buffered fragments ----
    uint32_t A0[2][4], A1[2][4], Bf[2][4][4];
    load_frags(xb, wb, 0, A0[0], A1[0], Bf[0]);
    #pragma unroll
    for (int s = 0; s < 12; s++) {
        int cur = s & 1, nxt = cur ^ 1;
        if (s < 11)
            load_frags(xb, wb, (uint32_t)(s + 1) * 32, A0[nxt], A1[nxt], Bf[nxt]);
        #pragma unroll
        for (int j = 0; j < 4; j++) {
            mma16816(acc[0][2*j],     A0[cur], Bf[cur][j][0], Bf[cur][j][2]);
            mma16816(acc[0][2*j + 1], A0[cur], Bf[cur][j][1], Bf[cur][j][3]);
            mma16816(acc[1][2*j],     A1[cur], Bf[cur][j][0], Bf[cur][j][2]);
            mma16816(acc[1][2*j + 1], A1[cur], Bf[cur][j][1], Bf[cur][j][3]);
        }
    }

    // ---- bias + relu in registers; per-row partial sums ----
    // thread holds 4 rows: idx i -> row = mgrp*32 + (lane>>2) + (i>>1)*16 + (i&1)*8
    const int c0 = ngrp * 64 + (lane & 3) * 2;
    float ysum[4] = {0.f, 0.f, 0.f, 0.f};
    float yss[4]  = {0.f, 0.f, 0.f, 0.f};
    #pragma unroll
    for (int mf = 0; mf < 2; mf++)
        #pragma unroll
        for (int nf = 0; nf < 8; nf++) {
            int c = c0 + nf * 8;
            float b0 = sPar[c], b1 = sPar[c + 1];
            float v0 = fmaxf(acc[mf][nf][0] + b0, 0.f);
            float v1 = fmaxf(acc[mf][nf][1] + b1, 0.f);
            float v2 = fmaxf(acc[mf][nf][2] + b0, 0.f);
            float v3 = fmaxf(acc[mf][nf][3] + b1, 0.f);
            acc[mf][nf][0] = v0; acc[mf][nf][1] = v1;
            acc[mf][nf][2] = v2; acc[mf][nf][3] = v3;
            ysum[mf*2]     += v0 + v1;
            yss[mf*2]      += v0*v0 + v1*v1;
            ysum[mf*2 + 1] += v2 + v3;
            yss[mf*2 + 1]  += v2*v2 + v3*v3;
        }
    // quad-reduce (lanes sharing a row differ in bits 0-1)
    #pragma unroll
    for (int i = 0; i < 4; i++) {
        ysum[i] += __shfl_xor_sync(0xffffffffu, ysum[i], 1);
        ysum[i] += __shfl_xor_sync(0xffffffffu, ysum[i], 2);
        yss[i]  += __shfl_xor_sync(0xffffffffu, yss[i],  1);
        yss[i]  += __shfl_xor_sync(0xffffffffu, yss[i],  2);
    }
    if ((lane & 3) == 0) {
        int r0 = mgrp * 32 + (lane >> 2);
        #pragma unroll
        for (int i = 0; i < 4; i++) {
            int r = r0 + (i >> 1) * 16 + (i & 1) * 8;
            sPart[r * 4 + ngrp] = make_float2(ysum[i], yss[i]);
        }
    }
    __syncthreads();

    // ---- finalize LN per row, write out from fragments ----
    #pragma unroll
    for (int i = 0; i < 4; i++) {
        int r = mgrp * 32 + (lane >> 2) + (i >> 1) * 16 + (i & 1) * 8;
        float4 pa = *(const float4*)&sPart[r * 4];
        float4 pb = *(const float4*)&sPart[r * 4 + 2];
        float sum = pa.x + pa.z + pb.x + pb.z;
        float ss  = pa.y + pa.w + pb.y + pb.w;
        float mean = sum * (1.f / 256.f);
        float var  = ss * (1.f / 256.f) - mean * mean;
        float rstd = rsqrtf(var + 1e-5f);
        float* orow = out + (size_t)(m_base + r) * CDIM;
        int mf = i >> 1, kp = (i & 1) * 2;
        #pragma unroll
        for (int nf = 0; nf < 8; nf++) {
            int c = c0 + nf * 8;
            float2 o2;
            o2.x = (acc[mf][nf][kp]     - mean) * rstd * sPar[256 + c]     + sPar[512 + c];
            o2.y = (acc[mf][nf][kp + 1] - mean) * rstd * sPar[256 + c + 1] + sPar[512 + c + 1];
            *(float2*)&orow[c] = o2;
        }
    }
}

// ============================================================
extern "C" void kernel_launch(void* const* d_in, const int* in_sizes, int n_in,
                              void* d_out, int out_size) {
    (void)in_sizes; (void)n_in; (void)out_size;
    const int*   user_input      = (const int*)  d_in[0];
    const float* emb             = (const float*)d_in[1];
    const int*   sc_country_idx  = (const int*)  d_in[2];
    const float* sc_country_emb  = (const float*)d_in[3];
    const int*   sc_device_idx   = (const int*)  d_in[4];
    const float* sc_device_emb   = (const float*)d_in[5];
    const int*   mf_tags_idx     = (const int*)  d_in[6];
    const float* mf_tags_emb     = (const float*)d_in[7];
    const int*   mf_history_idx  = (const int*)  d_in[8];
    const float* mf_history_emb  = (const float*)d_in[9];
    const float* fc_w            = (const float*)d_in[10];
    const float* fc_b            = (const float*)d_in[11];
    const float* ln_g            = (const float*)d_in[12];
    const float* ln_b            = (const float*)d_in[13];
    float* out = (float*)d_out;

    gather_kernel<<<GATHER_BLOCKS + WCONV_BLOCKS, 256>>>(
        user_input, emb,
        sc_country_idx, sc_country_emb,
        sc_device_idx,  sc_device_emb,
        mf_tags_idx,    mf_tags_emb,
        mf_history_idx, mf_history_emb,
        fc_w);

    cudaFuncSetAttribute(gemm_ln_mma_kernel,
                         cudaFuncAttributeMaxDynamicSharedMemorySize, SMEM_SZ);
    gemm_ln_mma_kernel<<<B_ROWS / 128, GEMM_THREADS, SMEM_SZ>>>(fc_b, ln_g, ln_b, out);
}